// round 17
// baseline (speedup 1.0000x reference)
#include <cuda_runtime.h>
#include <cuda_bf16.h>
#include <cuda_fp16.h>
#include <math_constants.h>
#include <cstdint>

#define N_ROWS   16384
#define N_CODES  8192
#define DIM      256

#define TM   128
#define TNI  128
#define NHALF    (N_CODES / 2)      // 4096 codes per CTA
#define ITERS    (NHALF / TNI)      // 32
#define LDAB  528
#define CAP   1024

#define AS_BYTES (128 * LDAB)
#define BS_BYTES (128 * LDAB)
#define OFF_B0   AS_BYTES
#define OFF_B1   (AS_BYTES + BS_BYTES)
#define OFF_RMIN (AS_BYTES + 2 * BS_BYTES)
#define OFF_MARG (OFF_RMIN + 128 * 4)
#define G_SMEM   (OFF_MARG + 128 * 4)

// ---------------------------------------------------------------------------
__device__ float         g_xx[N_ROWS];
__device__ float         g_ax[N_ROWS];
__device__ float         g_ww[N_CODES];
__device__ unsigned int  g_rowmin[N_ROWS];
__device__ unsigned int  g_cnt[N_ROWS];
__device__ uint2         g_cand[(size_t)N_ROWS * CAP];
__device__ int           g_idx[N_ROWS];
__device__ unsigned int  g_wmax;
__device__ __nv_bfloat16 g_xbf[N_ROWS * DIM];
__device__ __nv_bfloat16 g_wbf[N_CODES * DIM];

__device__ __forceinline__ unsigned int enc_f(float f) {
    unsigned int u = __float_as_uint(f);
    return (u & 0x80000000u) ? ~u : (u | 0x80000000u);
}
__device__ __forceinline__ float dec_f(unsigned int u) {
    return (u & 0x80000000u) ? __uint_as_float(u ^ 0x80000000u)
                             : __uint_as_float(~u);
}
__device__ __forceinline__ float row_margin(float ax, float xx, float wmaxv) {
    return 0.033f * ax * wmaxv + xx * 1.9073486e-6f + 2e-4f;
}
__device__ __forceinline__ void mma16816(float* c, const uint32_t* a,
                                         const uint32_t* b) {
    asm volatile(
        "mma.sync.aligned.m16n8k16.row.col.f32.bf16.bf16.f32 "
        "{%0,%1,%2,%3}, {%4,%5,%6,%7}, {%8,%9}, {%0,%1,%2,%3};"
        : "+f"(c[0]), "+f"(c[1]), "+f"(c[2]), "+f"(c[3])
        : "r"(a[0]), "r"(a[1]), "r"(a[2]), "r"(a[3]), "r"(b[0]), "r"(b[1]));
}
__device__ __forceinline__ void ldsm4(uint32_t* r, uint32_t addr) {
    asm volatile("ldmatrix.sync.aligned.m8n8.x4.shared.b16 {%0,%1,%2,%3}, [%4];"
                 : "=r"(r[0]), "=r"(r[1]), "=r"(r[2]), "=r"(r[3]) : "r"(addr));
}
__device__ __forceinline__ uint32_t smem_u32(const void* p) {
    uint32_t a;
    asm("{ .reg .u64 t; cvta.to.shared.u64 t, %1; cvt.u32.u64 %0, t; }"
        : "=r"(a) : "l"(p));
    return a;
}
__device__ __forceinline__ void cp16(uint32_t dst, const void* src) {
    asm volatile("cp.async.cg.shared.global [%0], [%1], 16;"
                 :: "r"(dst), "l"(src) : "memory");
}

// ---------------------------------------------------------------------------
// Kernel P: exact row stats + bf16 casts + wmax + per-row state init.
// ---------------------------------------------------------------------------
__global__ void prep_kernel(const float* __restrict__ x,
                            const float* __restrict__ w) {
    int t = blockIdx.x * blockDim.x + threadIdx.x;
    if (t < N_ROWS) {
        const float4* p = (const float4*)(x + (size_t)t * DIM);
        uint4* dst = (uint4*)(g_xbf + (size_t)t * DIM);
        float acc = 0.0f, aacc = 0.0f;
#pragma unroll 4
        for (int j = 0; j < 32; j++) {
            float4 v0 = p[2 * j], v1 = p[2 * j + 1];
            acc = __fadd_rn(acc, __fmul_rn(v0.x, v0.x));
            acc = __fadd_rn(acc, __fmul_rn(v0.y, v0.y));
            acc = __fadd_rn(acc, __fmul_rn(v0.z, v0.z));
            acc = __fadd_rn(acc, __fmul_rn(v0.w, v0.w));
            acc = __fadd_rn(acc, __fmul_rn(v1.x, v1.x));
            acc = __fadd_rn(acc, __fmul_rn(v1.y, v1.y));
            acc = __fadd_rn(acc, __fmul_rn(v1.z, v1.z));
            acc = __fadd_rn(acc, __fmul_rn(v1.w, v1.w));
            aacc += fabsf(v0.x) + fabsf(v0.y) + fabsf(v0.z) + fabsf(v0.w)
                  + fabsf(v1.x) + fabsf(v1.y) + fabsf(v1.z) + fabsf(v1.w);
            __nv_bfloat162 b0, b1, b2, b3;
            b0.x = __float2bfloat16_rn(v0.x); b0.y = __float2bfloat16_rn(v0.y);
            b1.x = __float2bfloat16_rn(v0.z); b1.y = __float2bfloat16_rn(v0.w);
            b2.x = __float2bfloat16_rn(v1.x); b2.y = __float2bfloat16_rn(v1.y);
            b3.x = __float2bfloat16_rn(v1.z); b3.y = __float2bfloat16_rn(v1.w);
            uint4 o;
            o.x = *(unsigned int*)&b0; o.y = *(unsigned int*)&b1;
            o.z = *(unsigned int*)&b2; o.w = *(unsigned int*)&b3;
            dst[j] = o;
        }
        g_xx[t] = acc;
        g_ax[t] = aacc;
        g_rowmin[t] = 0xFFFFFFFFu;
        g_cnt[t] = 0u;
    } else if (t < N_ROWS + N_CODES) {
        int r = t - N_ROWS;
        const float4* p = (const float4*)(w + (size_t)r * DIM);
        uint4* dst = (uint4*)(g_wbf + (size_t)r * DIM);
        float acc = 0.0f, amax = 0.0f;
#pragma unroll 4
        for (int j = 0; j < 32; j++) {
            float4 v0 = p[2 * j], v1 = p[2 * j + 1];
            acc = __fadd_rn(acc, __fmul_rn(v0.x, v0.x));
            acc = __fadd_rn(acc, __fmul_rn(v0.y, v0.y));
            acc = __fadd_rn(acc, __fmul_rn(v0.z, v0.z));
            acc = __fadd_rn(acc, __fmul_rn(v0.w, v0.w));
            acc = __fadd_rn(acc, __fmul_rn(v1.x, v1.x));
            acc = __fadd_rn(acc, __fmul_rn(v1.y, v1.y));
            acc = __fadd_rn(acc, __fmul_rn(v1.z, v1.z));
            acc = __fadd_rn(acc, __fmul_rn(v1.w, v1.w));
            amax = fmaxf(amax, fmaxf(fmaxf(fabsf(v0.x), fabsf(v0.y)),
                                     fmaxf(fabsf(v0.z), fabsf(v0.w))));
            amax = fmaxf(amax, fmaxf(fmaxf(fabsf(v1.x), fabsf(v1.y)),
                                     fmaxf(fabsf(v1.z), fabsf(v1.w))));
            __nv_bfloat162 b0, b1, b2, b3;
            b0.x = __float2bfloat16_rn(v0.x); b0.y = __float2bfloat16_rn(v0.y);
            b1.x = __float2bfloat16_rn(v0.z); b1.y = __float2bfloat16_rn(v0.w);
            b2.x = __float2bfloat16_rn(v1.x); b2.y = __float2bfloat16_rn(v1.y);
            b3.x = __float2bfloat16_rn(v1.z); b3.y = __float2bfloat16_rn(v1.w);
            uint4 o;
            o.x = *(unsigned int*)&b0; o.y = *(unsigned int*)&b1;
            o.z = *(unsigned int*)&b2; o.w = *(unsigned int*)&b3;
            dst[j] = o;
        }
        g_ww[r] = acc;
        atomicMax(&g_wmax, __float_as_uint(amax));
    }
}

// ---------------------------------------------------------------------------
// Kernel G: persistent-A GEMM. grid=(2,128): y = row block, x = code half.
// 512 threads, 16 warps in 4x4 (warp tile 32 rows x 32 cols).
// CTA-local smem rmins over its code half (>= global min => superset filter);
// g_rowmin merged by atomicMin; candidate slots via global atomicAdd.
// ---------------------------------------------------------------------------
__global__ void __launch_bounds__(512)
vq_gemm_kernel() {
    extern __shared__ char sm[];
    char* As = sm;
    unsigned int* rmins = (unsigned int*)(sm + OFF_RMIN);
    float*        margs = (float*)(sm + OFF_MARG);

    const int tid  = threadIdx.x;
    const int wid  = tid >> 5;
    const int lane = tid & 31;
    const int wm   = wid & 3;      // 0..3 -> 32 rows
    const int wn   = wid >> 2;     // 0..3 -> 32 cols
    const int g    = lane >> 2;
    const int tg   = lane & 3;
    const int rowBase = blockIdx.y * TM;
    const int cbase0  = blockIdx.x * NHALF;

    const uint32_t sm_u  = smem_u32(sm);
    const uint32_t As_u  = sm_u;
    const uint32_t Bu[2] = {sm_u + OFF_B0, sm_u + OFF_B1};

    // prologue: prefetch B tile 0
#pragma unroll
    for (int i = 0; i < 8; i++) {
        int c = tid + i * 512;
        int r = c >> 5;
        int k16 = c & 31;
        cp16(Bu[0] + r * LDAB + k16 * 16,
             g_wbf + (size_t)(cbase0 + r) * DIM + k16 * 8);
    }
    asm volatile("cp.async.commit_group;" ::: "memory");

    // stage A (once)
#pragma unroll
    for (int i = 0; i < 8; i++) {
        int c = tid + i * 512;
        int r = c >> 5;
        int k16 = c & 31;
        uint4 v = *(const uint4*)(g_xbf + (size_t)(rowBase + r) * DIM + k16 * 8);
        *(uint4*)(As + r * LDAB + k16 * 16) = v;
    }
    if (tid < 128) {
        rmins[tid] = 0xFFFFFFFFu;
        int row = rowBase + tid;
        margs[tid] = 0.5f * row_margin(g_ax[row], g_xx[row],
                                       __uint_as_float(g_wmax));
    }
    asm volatile("cp.async.wait_group 0;" ::: "memory");
    __syncthreads();

    const int lrow  = (lane & 7) + ((lane >> 3) & 1) * 8;
    const int lkoff = ((lane >> 4) & 1) * 16;

#pragma unroll 1
    for (int it = 0; it < ITERS; it++) {
        // prefetch next B tile
        if (it + 1 < ITERS) {
            const int nb = cbase0 + (it + 1) * TNI;
#pragma unroll
            for (int i = 0; i < 8; i++) {
                int c = tid + i * 512;
                int r = c >> 5;
                int k16 = c & 31;
                cp16(Bu[(it + 1) & 1] + r * LDAB + k16 * 16,
                     g_wbf + (size_t)(nb + r) * DIM + k16 * 8);
            }
        }
        asm volatile("cp.async.commit_group;" ::: "memory");

        float acc[2][4][4];
#pragma unroll
        for (int mi = 0; mi < 2; mi++)
#pragma unroll
            for (int ni = 0; ni < 4; ni++)
#pragma unroll
                for (int e = 0; e < 4; e++) acc[mi][ni][e] = 0.0f;

        const uint32_t Bcur = Bu[it & 1];
#pragma unroll
        for (int ks = 0; ks < 16; ks++) {
            uint32_t a[2][4];
#pragma unroll
            for (int mi = 0; mi < 2; mi++)
                ldsm4(a[mi], As_u + (wm * 32 + mi * 16 + lrow) * LDAB
                             + ks * 32 + lkoff);
            uint32_t b[4][2];
#pragma unroll
            for (int np = 0; np < 2; np++) {
                uint32_t r[4];
                ldsm4(r, Bcur + (wn * 32 + np * 16 + lrow) * LDAB
                         + ks * 32 + lkoff);
                b[2 * np][0]     = r[0]; b[2 * np][1]     = r[2];
                b[2 * np + 1][0] = r[1]; b[2 * np + 1][1] = r[3];
            }
#pragma unroll
            for (int mi = 0; mi < 2; mi++)
#pragma unroll
                for (int ni = 0; ni < 4; ni++)
                    mma16816(acc[mi][ni], a[mi], b[ni]);
        }

        // distances + running smem rowmin (over this CTA's code half)
        const int c0 = cbase0 + it * TNI + wn * 32 + tg * 2;
#pragma unroll
        for (int mi = 0; mi < 2; mi++) {
            float mlo = CUDART_INF_F, mhi = CUDART_INF_F;
#pragma unroll
            for (int ni = 0; ni < 4; ni++) {
                float ww0 = __ldg(&g_ww[c0 + ni * 8]);
                float ww1 = __ldg(&g_ww[c0 + ni * 8 + 1]);
                acc[mi][ni][0] = __fmaf_rn(-2.0f, acc[mi][ni][0], ww0);
                acc[mi][ni][1] = __fmaf_rn(-2.0f, acc[mi][ni][1], ww1);
                acc[mi][ni][2] = __fmaf_rn(-2.0f, acc[mi][ni][2], ww0);
                acc[mi][ni][3] = __fmaf_rn(-2.0f, acc[mi][ni][3], ww1);
                mlo = fminf(mlo, fminf(acc[mi][ni][0], acc[mi][ni][1]));
                mhi = fminf(mhi, fminf(acc[mi][ni][2], acc[mi][ni][3]));
            }
            mlo = fminf(mlo, __shfl_xor_sync(0xFFFFFFFF, mlo, 1));
            mlo = fminf(mlo, __shfl_xor_sync(0xFFFFFFFF, mlo, 2));
            mhi = fminf(mhi, __shfl_xor_sync(0xFFFFFFFF, mhi, 1));
            mhi = fminf(mhi, __shfl_xor_sync(0xFFFFFFFF, mhi, 2));
            if (tg == 0) {
                atomicMin(&rmins[wm * 32 + mi * 16 + g], enc_f(mlo));
                atomicMin(&rmins[wm * 32 + mi * 16 + g + 8], enc_f(mhi));
            }
        }

        asm volatile("cp.async.wait_group 0;" ::: "memory");
        __syncthreads();

        // push candidates within running-min + margin (superset of final set)
#pragma unroll
        for (int mi = 0; mi < 2; mi++) {
#pragma unroll
            for (int h = 0; h < 2; h++) {
                int rl = wm * 32 + mi * 16 + g + h * 8;
                int row = rowBase + rl;
                float thr = dec_f(rmins[rl]) + margs[rl];
#pragma unroll
                for (int ni = 0; ni < 4; ni++) {
#pragma unroll
                    for (int q = 0; q < 2; q++) {
                        float d = acc[mi][ni][h * 2 + q];
                        if (d <= thr) {
                            int code = c0 + ni * 8 + q;
                            unsigned int slot = atomicAdd(&g_cnt[row], 1u);
                            if (slot < CAP)
                                g_cand[(size_t)row * CAP + slot] =
                                    make_uint2(enc_f(d), (unsigned int)code);
                        }
                    }
                }
            }
        }
    }

    __syncthreads();
    if (tid < 128)
        atomicMin(&g_rowmin[rowBase + tid], rmins[tid]);  // merge halves
}

// ---------------------------------------------------------------------------
// Kernel F: per-row candidate rescore (exact fp32, first-index ties).
// ---------------------------------------------------------------------------
__global__ void __launch_bounds__(256)
select_kernel(const float* __restrict__ x, const float* __restrict__ w) {
    const int row  = blockIdx.x * 8 + (threadIdx.x >> 5);
    const int lane = threadIdx.x & 31;

    const float wmaxv = __uint_as_float(g_wmax);
    const float xx = g_xx[row];
    const float thr = dec_f(g_rowmin[row]) + row_margin(g_ax[row], xx, wmaxv);
    const unsigned int cnt = g_cnt[row];
    const float* xr = x + (size_t)row * DIM;

    float bv = CUDART_INF_F;
    int   bi = 0x7fffffff;

    if (cnt <= CAP) {
        const uint2* cl = g_cand + (size_t)row * CAP;
        for (unsigned int s = lane; s < cnt; s += 32) {
            uint2 c = cl[s];
            if (dec_f(c.x) <= thr) {
                int code = (int)c.y;
                const float* wr = w + (size_t)code * DIM;
                float sdot = 0.0f;
#pragma unroll 8
                for (int k = 0; k < DIM; k++)
                    sdot = __fmaf_rn(xr[k], wr[k], sdot);
                float tq = __fadd_rn(xx, g_ww[code]);
                float dq = __fadd_rn(tq, __fmul_rn(-2.0f, sdot));
                if (dq < bv || (dq == bv && code < bi)) { bv = dq; bi = code; }
            }
        }
    } else {
        for (int code = lane; code < N_CODES; code += 32) {
            const float* wr = w + (size_t)code * DIM;
            float sdot = 0.0f;
#pragma unroll 8
            for (int k = 0; k < DIM; k++)
                sdot = __fmaf_rn(xr[k], wr[k], sdot);
            float tq = __fadd_rn(xx, g_ww[code]);
            float dq = __fadd_rn(tq, __fmul_rn(-2.0f, sdot));
            if (dq < bv || (dq == bv && code < bi)) { bv = dq; bi = code; }
        }
    }
#pragma unroll
    for (int off = 16; off > 0; off >>= 1) {
        float ov = __shfl_xor_sync(0xFFFFFFFF, bv, off);
        int   oi = __shfl_xor_sync(0xFFFFFFFF, bi, off);
        if (ov < bv || (ov == bv && oi < bi)) { bv = ov; bi = oi; }
    }
    if (lane == 0) g_idx[row] = bi;
}

// ---------------------------------------------------------------------------
__global__ void gather_kernel(const float* __restrict__ w, float* __restrict__ out,
                              int out_size) {
    int i = blockIdx.x * blockDim.x + threadIdx.x;
    if (i < N_ROWS * (DIM / 4)) {
        int row = i >> 6;
        int c = i & 63;
        int k = g_idx[row];
        float4 v = ((const float4*)(w + (size_t)k * DIM))[c];
        ((float4*)out)[i] = v;
    }
    if (i < N_ROWS && out_size >= N_ROWS * DIM + N_ROWS) {
        out[N_ROWS * DIM + i] = (float)g_idx[i];
    }
}

// ---------------------------------------------------------------------------
extern "C" void kernel_launch(void* const* d_in, const int* in_sizes, int n_in,
                              void* d_out, int out_size) {
    const float* x = (const float*)d_in[0];
    const float* w = (const float*)d_in[1];
    float* out = (float*)d_out;

    static bool attr_set = false;
    if (!attr_set) {
        cudaFuncSetAttribute(vq_gemm_kernel,
                             cudaFuncAttributeMaxDynamicSharedMemorySize, G_SMEM);
        attr_set = true;
    }

    {
        int total = N_ROWS + N_CODES;
        prep_kernel<<<(total + 255) / 256, 256>>>(x, w);
    }
    {
        dim3 grid(2, N_ROWS / TM);   // (code half, row block) = 256 CTAs
        vq_gemm_kernel<<<grid, 512, G_SMEM>>>();
    }
    {
        select_kernel<<<N_ROWS / 8, 256>>>(x, w);
    }
    {
        int total4 = N_ROWS * (DIM / 4);
        gather_kernel<<<(total4 + 255) / 256, 256>>>(w, out, out_size);
    }
}